// round 15
// baseline (speedup 1.0000x reference)
#include <cuda_runtime.h>
#include <stdint.h>

// ---------------------------------------------------------------------------
// VanDerWallsSurface: scatter point features into a 128^3 voxel grid.
//  out[b,x,y,z] = [max f0, min f1, mean f2] over points whose sphere covers
//  the voxel (within the 5x5x5 neighborhood of round(coords)), else zeros.
//
// R14: hide the scatter under the output write stream (intra-block fusion).
//  Evidence: sweep is pinned at ~27us (=write ceiling ~3.7TB/s) across scalar
//  /float4/TMA stores -> only the ~10us serialized scatter is recoverable.
//  R6's fusion failed because scatter and zero work were in DIFFERENT blocks
//  (separate dispatch waves -> serialized). R14 interleaves INSIDE each
//  block: 3 fire-and-forget float4 zero-stores per thread, then 2 points of
//  scatter (RED atomics, no result) -> every wave mixes write-stream + 
//  latency work. Kernel 2 only fixes dirty lines via the bitmap (~9k lines:
//  decode, 96B overwrite, Acc clean) and clears its bitmap words.
//
//  - Order-preserving uint encodings make 0 the neutral element for all four
//    accumulators -> scratch is a zero-initialized static; K2 re-zeroes dirty
//    Acc lines and bitmap words: all-zero invariant across graph replays.
// ---------------------------------------------------------------------------

#define VOL        128
#define NB         4
#define NPTS       4096
#define NPOINTS    (NB * NPTS)            // 16384
#define KOFF       125                    // 5x5x5 offsets
#define TOTAL_VOX  (NB * VOL * VOL * VOL) // 8,388,608
#define NLINES     (TOTAL_VOX / 8)        // 1,048,576 (8 Acc per 128B line)
#define NWORDS     (NLINES / 32)          // 32,768 bitmap words
#define TPB        256

#define K1_BLOCKS  (NPOINTS / 2)          // 8,192 (2 points + 768 float4 each)
#define F4_PER_BLK 768                    // 6,291,456 / 8192
#define K2_BLOCKS  (NLINES / TPB)         // 4,096
#define WPB        8                      // bitmap words per K2 block

// Interleaved per-voxel accumulator: one 128B cache line covers all four
// fields of 8 z-adjacent voxels. All neutral elements are 0.
struct Acc {
    unsigned int maxk;  // max-key of f0
    unsigned int mink;  // ~min-key of f1 (min via max)
    unsigned int cnt;   // hit count
    float        sum;   // sum of f2
};
__device__ Acc          g_acc[TOTAL_VOX];  // zero-init; kept zero by k_fixup
__device__ unsigned int g_dirty[NWORDS];   // 1 bit per Acc line; cleared by k_fixup

// Order-preserving float -> uint key. For any finite non-NaN f, fkey(f) > 0,
// so 0 is a valid "empty" sentinel for atomicMax accumulation.
__device__ __forceinline__ unsigned int fkey(float f) {
    unsigned int u = __float_as_uint(f);
    return (u & 0x80000000u) ? ~u : (u | 0x80000000u);
}
__device__ __forceinline__ float funkey(unsigned int k) {
    unsigned int u = (k & 0x80000000u) ? (k ^ 0x80000000u) : ~k;
    return __uint_as_float(u);
}

// Kernel 1: every block does BOTH kinds of work so the two streams overlap
// chip-wide: (a) zero 768 output float4 (fire-and-forget stores), then
// (b) scatter 2 points x 125 offsets (RED atomics into the interleaved Acc
// + dirty-bit OR). Atomics' results are unused -> no completion dependency.
__global__ void __launch_bounds__(TPB) k_zero_scatter(
    const float4* __restrict__ cr,     // (B*N) x [cx, cy, cz, r]
    const float*  __restrict__ feat,   // (B*N) x 3
    float4*       __restrict__ out4)   // d_out viewed as float4
{
    unsigned bid = blockIdx.x;
    unsigned tid = threadIdx.x;

    // (a) output zeroing: 3 independent STG.128 per thread, contiguous block
    // region [bid*768, bid*768+768) float4.
    {
        float4 z = make_float4(0.f, 0.f, 0.f, 0.f);
        size_t base = (size_t)bid * F4_PER_BLK + tid;
        out4[base]       = z;
        out4[base + 256] = z;
        out4[base + 512] = z;
    }

    // (b) scatter: threads [0,125) -> point 2*bid, threads [125,250) -> 2*bid+1.
    if (tid >= 250) return;
    int pn = bid * 2 + (tid >= 125 ? 1 : 0);
    int k  = (tid >= 125) ? (int)tid - 125 : (int)tid;

    float4 c = __ldg(cr + pn);

    int ox = k / 25 - 2;
    int oy = (k / 5) % 5 - 2;
    int oz = k % 5 - 2;

    // jnp.round == round-half-to-even == rn conversions
    int vx = __float2int_rn(c.x) + ox;
    int vy = __float2int_rn(c.y) + oy;
    int vz = __float2int_rn(c.z) + oz;

    // Exact IEEE ops, left-to-right sum, matching the reference (no FMA
    // contraction that could flip sphere-boundary membership).
    float dx = __fsub_rn((float)vx, c.x);
    float dy = __fsub_rn((float)vy, c.y);
    float dz = __fsub_rn((float)vz, c.z);
    float d2 = __fadd_rn(__fadd_rn(__fmul_rn(dx, dx), __fmul_rn(dy, dy)),
                         __fmul_rn(dz, dz));

    float rr = __fdiv_rn(rintf(__fmul_rn(c.w, 1000.0f)), 1000.0f);
    float r2 = __fmul_rn(rr, rr);

    bool ok = (d2 <= r2)
            && ((unsigned)vx < VOL) && ((unsigned)vy < VOL) && ((unsigned)vz < VOL);
    if (!ok) return;

    unsigned e = (unsigned)((pn >> 12) * (VOL * VOL * VOL)
                            + ((vx * VOL + vy) * VOL + vz));

    const float* fp = feat + (size_t)pn * 3;
    float f0 = __ldg(fp + 0);
    float f1 = __ldg(fp + 1);
    float f2 = __ldg(fp + 2);

    Acc* a = &g_acc[e];
    atomicMax(&a->maxk, fkey(f0));      // results unused -> RED (fire-&-forget)
    atomicMax(&a->mink, ~fkey(f1));     // min via max of complemented key
    atomicAdd(&a->cnt, 1u);
    atomicAdd(&a->sum, f2);

    unsigned line = e >> 3;             // 8 Acc per 128B line
    atomicOr(&g_dirty[line >> 5], 1u << (line & 31u));
}

// Kernel 2: dirty-line fixup. One thread per Acc line; block owns lines
// [b*256, +256) = bitmap words [b*8, +8) (staged in smem). Dirty thread:
// read its 128B Acc line, decode 8 voxels, overwrite the 96B output block
// (already zeroed by K1), zero the Acc line (thread-exclusive ownership ->
// read-then-zero within one thread is race-free). Then clear dirty words.
__global__ void __launch_bounds__(TPB) k_fixup(float4* __restrict__ out4)
{
    __shared__ unsigned s_w[WPB];
    unsigned b = blockIdx.x;
    if (threadIdx.x < WPB) s_w[threadIdx.x] = g_dirty[b * WPB + threadIdx.x];
    __syncthreads();

    unsigned w = s_w[threadIdx.x >> 5];               // warp-uniform
    if ((w >> (threadIdx.x & 31u)) & 1u) {
        size_t L = (size_t)b * TPB + threadIdx.x;     // line id
        uint4* accl = reinterpret_cast<uint4*>(g_acc) + L * 8;

        float o[24];                                  // 8 voxels x 3 channels
#pragma unroll
        for (int j = 0; j < 8; j++) {
            uint4 a = accl[j];
            float v0 = 0.0f, v1 = 0.0f, v2 = 0.0f;
            if (a.z != 0u) {                          // cnt != 0
                v0 = funkey(a.x);
                v1 = funkey(~a.y);
                v2 = __fdiv_rn(__uint_as_float(a.w), (float)a.z);
            }
            o[j * 3 + 0] = v0;
            o[j * 3 + 1] = v1;
            o[j * 3 + 2] = v2;
        }

        uint4 z = make_uint4(0u, 0u, 0u, 0u);
#pragma unroll
        for (int j = 0; j < 8; j++) accl[j] = z;      // self-clean (own line)

        float4* ob = out4 + L * 6;                    // 96B output block
#pragma unroll
        for (int j = 0; j < 6; j++)
            ob[j] = make_float4(o[j*4+0], o[j*4+1], o[j*4+2], o[j*4+3]);
    }

    // Clear this block's dirty words (s_w was loaded before the barrier; each
    // word is owned exclusively by this block).
    if (threadIdx.x < WPB && s_w[threadIdx.x] != 0u)
        g_dirty[b * WPB + threadIdx.x] = 0u;
}

extern "C" void kernel_launch(void* const* d_in, const int* in_sizes, int n_in,
                              void* d_out, int out_size)
{
    const float4* cr   = (const float4*)d_in[0];  // coordinates_radii (B,N,4)
    const float*  feat = (const float*)d_in[1];   // features (B,N,3)
    float4*       out4 = (float4*)d_out;          // (B,128,128,128,3) f32

    k_zero_scatter<<<K1_BLOCKS, TPB>>>(cr, feat, out4);
    k_fixup<<<K2_BLOCKS, TPB>>>(out4);
}

// round 16
// speedup vs baseline: 1.3035x; 1.3035x over previous
#include <cuda_runtime.h>
#include <stdint.h>

// ---------------------------------------------------------------------------
// VanDerWallsSurface: scatter point features into a 128^3 voxel grid.
//  out[b,x,y,z] = [max f0, min f1, mean f2] over points whose sphere covers
//  the voxel (within the 5x5x5 neighborhood of round(coords)), else zeros.
//
// R15: R11 structure (best) + a cheaper scatter.
//  Evidence: sweep is pinned at ~27us (write ceiling, measured identical
//  across scalar/float4/TMA stores, R5..R13); fusion attempts (R6, R14) both
//  lost to drain contention. Only the ~10us scatter is recoverable.
//  R15 scatter: 1 warp/point, lanes 0..24 = (ox,oy) columns, 5-z loop per
//  column. Exact column pruning (dxy^2 > r^2 or x/y OOB kills all 5 z).
//  cnt+sum packed into ONE 64-bit fixed-point atomicAdd (delta = 2^45 +
//  round(f2 * 2^24)): 4 atomics/hit -> 3. Dirty-bit ORs deduped per column.
//  Sweep: R11's kernel verbatim, with the packed-cnt/sum decode.
//
//  - Order-preserving uint encodings make 0 the neutral element for all
//    accumulators -> scratch is a zero-initialized static; the sweep re-zeroes
//    dirty Acc entries and its bitmap words: all-zero across graph replays.
// ---------------------------------------------------------------------------

#define VOL        128
#define NB         4
#define NPTS       4096
#define NPOINTS    (NB * NPTS)            // 16384
#define TOTAL_VOX  (NB * VOL * VOL * VOL) // 8,388,608
#define NLINES     (TOTAL_VOX / 8)        // 1,048,576 (8 Acc per 128B line)
#define NWORDS     (NLINES / 32)          // 32,768 bitmap words
#define TPB        256

#define SCAT_BLOCKS  (NPOINTS * 32 / TPB) // 2,048 (1 warp per point)
#define WPB          8                    // bitmap words per sweep block
#define SWEEP_BLOCKS (NWORDS / WPB)       // 4,096

#define SUM_SCALE    16777216.0           // 2^24 fixed-point for f2 sums
#define CNT_SHIFT    45

// Interleaved per-voxel accumulator (16B): maxk, mink, packed cnt|sum.
// All neutral elements are 0.
struct __align__(16) Acc {
    unsigned int       maxk;    // max-key of f0
    unsigned int       mink;    // ~min-key of f1 (min via max)
    unsigned long long cntsum;  // cnt*2^45 + round(sum(f2)*2^24) (2's compl)
};
__device__ Acc          g_acc[TOTAL_VOX];  // zero-init; kept zero by k_sweep
__device__ unsigned int g_dirty[NWORDS];   // 1 bit per Acc line; cleared by k_sweep

// Order-preserving float -> uint key. For any finite non-NaN f, fkey(f) > 0,
// so 0 is a valid "empty" sentinel for atomicMax accumulation.
__device__ __forceinline__ unsigned int fkey(float f) {
    unsigned int u = __float_as_uint(f);
    return (u & 0x80000000u) ? ~u : (u | 0x80000000u);
}
__device__ __forceinline__ float funkey(unsigned int k) {
    unsigned int u = (k & 0x80000000u) ? (k ^ 0x80000000u) : ~k;
    return __uint_as_float(u);
}

// Kernel A: one warp per point. Lanes 0..24 are the 25 (ox,oy) columns; each
// loops over the 5 z-offsets. Column pruning: x/y OOB or dxy2 > r2 -> the
// whole column can't hit (dz^2 >= 0). Hits: 2 atomicMax + 1 packed atomicAdd.
// Dirty-line ORs are accumulated per bitmap word within the column (<=2 ORs).
__global__ void __launch_bounds__(TPB) k_scatter(
    const float4* __restrict__ cr,     // (B*N) x [cx, cy, cz, r]
    const float*  __restrict__ feat)   // (B*N) x 3
{
    int pn   = (blockIdx.x * TPB + threadIdx.x) >> 5;  // point id (warp-uniform)
    int lane = threadIdx.x & 31;

    float4 c = __ldg(cr + pn);          // warp-uniform -> single broadcast
    if (lane >= 25) return;

    int ox = lane / 5 - 2;
    int oy = lane % 5 - 2;

    // jnp.round == round-half-to-even == rn conversions
    int vx = __float2int_rn(c.x) + ox;
    int vy = __float2int_rn(c.y) + oy;
    int rz = __float2int_rn(c.z);
    if (((unsigned)vx >= VOL) | ((unsigned)vy >= VOL)) return;

    // Exact IEEE ops, left-to-right, matching the reference:
    // d2 = (dx*dx + dy*dy) + dz*dz  with rn at every step, no FMA contraction.
    float dx   = __fsub_rn((float)vx, c.x);
    float dy   = __fsub_rn((float)vy, c.y);
    float dxy2 = __fadd_rn(__fmul_rn(dx, dx), __fmul_rn(dy, dy));

    float rr = __fdiv_rn(rintf(__fmul_rn(c.w, 1000.0f)), 1000.0f);
    float r2 = __fmul_rn(rr, rr);
    if (dxy2 > r2) return;              // exact column prune

    const float* fp = feat + (size_t)pn * 3;
    float f0 = __ldg(fp + 0);
    float f1 = __ldg(fp + 1);
    float f2 = __ldg(fp + 2);
    unsigned mk = fkey(f0);
    unsigned nk = ~fkey(f1);
    unsigned long long ps = (1ULL << CNT_SHIFT)
        + (unsigned long long)__double2ll_rn((double)f2 * SUM_SCALE);

    unsigned ebase = (unsigned)((pn >> 12) * (VOL * VOL * VOL)
                                + ((vx * VOL + vy) * VOL));

    unsigned pendWord = 0xFFFFFFFFu;    // deduped dirty-OR accumulator
    unsigned pendBits = 0u;

#pragma unroll
    for (int oz = -2; oz <= 2; oz++) {
        int vz = rz + oz;
        if ((unsigned)vz >= VOL) continue;
        float dz = __fsub_rn((float)vz, c.z);
        float d2 = __fadd_rn(dxy2, __fmul_rn(dz, dz));
        if (d2 > r2) continue;

        unsigned e = ebase + (unsigned)vz;
        Acc* a = &g_acc[e];
        atomicMax(&a->maxk, mk);        // results unused -> RED
        atomicMax(&a->mink, nk);
        atomicAdd(&a->cntsum, ps);      // packed cnt + fixed-point sum

        unsigned line = e >> 3;         // 8 Acc per 128B line
        unsigned word = line >> 5;
        if (word != pendWord) {
            if (pendWord != 0xFFFFFFFFu) atomicOr(&g_dirty[pendWord], pendBits);
            pendWord = word;
            pendBits = 0u;
        }
        pendBits |= 1u << (line & 31u);
    }
    if (pendWord != 0xFFFFFFFFu) atomicOr(&g_dirty[pendWord], pendBits);
}

// Kernel B (R11's proven sweep): block handles WPB=8 bitmap words (8 x 256
// voxels). Clean voxel -> 12B of zeros; dirty line -> 16B Acc read (L2-hot),
// decode, 12B out, 16B Acc clean. Plain write-back stores. After the loop,
// one barrier, then threads 0..7 clear their dirty words.
__global__ void __launch_bounds__(TPB) k_sweep(float* __restrict__ out)
{
    unsigned b = blockIdx.x;
    unsigned dirtyflags = 0u;

#pragma unroll
    for (int it = 0; it < WPB; it++) {
        unsigned widx = b * WPB + it;
        unsigned w = g_dirty[widx];                // block-uniform broadcast
        dirtyflags |= (w != 0u ? 1u : 0u) << it;

        unsigned e = widx * 256 + threadIdx.x;     // voxel id
        size_t   o = (size_t)e * 3;                // 12B/thread, coalesced

        if (((w >> ((threadIdx.x >> 3) & 31u)) & 1u) == 0u) {  // clean line
            out[o + 0] = 0.0f;
            out[o + 1] = 0.0f;
            out[o + 2] = 0.0f;
        } else {
            uint4* ap = reinterpret_cast<uint4*>(g_acc) + e;   // lane-dense
            uint4 a = *ap;
            float v0 = 0.0f, v1 = 0.0f, v2 = 0.0f;
            unsigned long long cs =
                ((unsigned long long)a.w << 32) | (unsigned long long)a.z;
            if (cs != 0ull) {                      // cnt != 0
                long long t   = (long long)cs;
                long long cnt = (t + (1LL << (CNT_SHIFT - 1))) >> CNT_SHIFT;
                long long s   = t - (cnt << CNT_SHIFT);
                v0 = funkey(a.x);
                v1 = funkey(~a.y);
                float sf = (float)((double)s * (1.0 / SUM_SCALE));
                v2 = __fdiv_rn(sf, (float)cnt);
                *ap = make_uint4(0u, 0u, 0u, 0u);  // self-clean for next call
            }
            out[o + 0] = v0;
            out[o + 1] = v1;
            out[o + 2] = v2;
        }
    }

    // All threads have consumed their words; clear the dirty ones.
    __syncthreads();
    if (threadIdx.x < WPB && ((dirtyflags >> threadIdx.x) & 1u))
        g_dirty[b * WPB + threadIdx.x] = 0u;
}

extern "C" void kernel_launch(void* const* d_in, const int* in_sizes, int n_in,
                              void* d_out, int out_size)
{
    const float4* cr   = (const float4*)d_in[0];  // coordinates_radii (B,N,4)
    const float*  feat = (const float*)d_in[1];   // features (B,N,3)
    float*        out  = (float*)d_out;           // (B,128,128,128,3) f32

    k_scatter<<<SCAT_BLOCKS, TPB>>>(cr, feat);
    k_sweep<<<SWEEP_BLOCKS, TPB>>>(out);
}